// round 3
// baseline (speedup 1.0000x reference)
#include <cuda_runtime.h>

// ---------------- problem constants (fixed by the dataset) ----------------
#define NN   100000     // nodes
#define NE   1600000    // edges
#define NGR  256        // graphs
#define NF   64         // node feat
#define NF2  128        // 2*NF
#define EFB  40         // rbf bins
#define NL   3          // layers
#define NAT  95         // atom types
#define NAF  200        // atom feat
#define TAB  2048       // e_lin interpolation intervals over [0,8]
#define BN_EPS 1e-5f

// ---------------- persistent device scratch (no runtime allocation) -------
__device__ float g_x   [NN * NF];          // node features
__device__ float g_hs  [NN * NF2];         // x @ W_src + b
__device__ float g_hd  [NN * NF2];         // x @ W_dst + b
__device__ float g_h   [NN * NF];          // scattered messages
__device__ float g_tab [(TAB + 1) * NF2];  // e_lin(d) lerp table (per layer)
__device__ float g_emb [NAT * NF];         // atom_table @ W_embed + b
__device__ float g_esum[NF2];
__device__ float g_esq [NF2];
__device__ float g_AB  [2 * NF2];          // folded BN: A*m+B
__device__ float g_nsum[NF];
__device__ float g_nsq [NF];
__device__ float g_pool[NGR * NF];
__device__ float g_cnt [NGR];

// ---------------- helpers -------------------------------------------------
__device__ __forceinline__ float sp_f(float x) {   // softplus = max(x,0)+log1p(exp(-|x|))
    return fmaxf(x, 0.0f) + __logf(1.0f + __expf(-fabsf(x)));
}
__device__ __forceinline__ float sig_f(float x) {
    return __fdividef(1.0f, 1.0f + __expf(-x));
}

// --------------- 0a: fold atom featurizer + embedding into [95,64] --------
__global__ void k_emb(const float* __restrict__ at, const float* __restrict__ W,
                      const float* __restrict__ b) {
    int a = blockIdx.x, c = threadIdx.x;               // 95 blocks x 64 threads
    float acc = b[c];
    for (int k = 0; k < NAF; ++k)
        acc += at[a * NAF + k] * W[k * NF + c];
    g_emb[a * NF + c] = acc;
}

// --------------- 0b: x[n] = emb[type[n]] ----------------------------------
__global__ void k_gather_x(const int* __restrict__ types) {
    int i = blockIdx.x * blockDim.x + threadIdx.x;
    const int total = NN * (NF / 4);
    for (; i < total; i += gridDim.x * blockDim.x) {
        int n = i >> 4, j = i & 15;
        int t = __ldg(&types[n]);
        reinterpret_cast<float4*>(g_x)[i] =
            reinterpret_cast<const float4*>(g_emb)[t * (NF / 4) + j];
    }
}

// --------------- per-layer: build e_lin(d) lerp table ---------------------
__global__ void k_tab(const float* __restrict__ We, const float* __restrict__ be, int l) {
    __shared__ float phi[EFB];
    const float d = blockIdx.x * (8.0f / TAB);
    const int c = threadIdx.x;                          // 128 threads
    if (c < EFB) {
        float ctr = c * (8.0f / 39.0f);                 // linspace(0,8,40)
        float x = d - ctr;
        phi[c] = expf(-4.875f * x * x);                 // gamma = 39/8
    }
    __syncthreads();
    const float* W = We + l * EFB * NF2;
    float acc = be[l * NF2 + c];
#pragma unroll
    for (int k = 0; k < EFB; ++k)
        acc += phi[k] * W[k * NF2 + c];
    g_tab[blockIdx.x * NF2 + c] = acc;
}

// --------------- small zeroing kernels ------------------------------------
__global__ void k_zero_small() {
    int t = threadIdx.x;                                // 384 threads
    if (t < NF2) { g_esum[t] = 0.0f; g_esq[t] = 0.0f; }
    else if (t < NF2 + NF)       g_nsum[t - NF2] = 0.0f;
    else if (t < NF2 + 2 * NF)   g_nsq [t - NF2 - NF] = 0.0f;
}
__global__ void k_zero_h() {
    int i = blockIdx.x * blockDim.x + threadIdx.x;
    const int total = NN * (NF / 4);
    float4 z = make_float4(0.f, 0.f, 0.f, 0.f);
    for (; i < total; i += gridDim.x * blockDim.x)
        reinterpret_cast<float4*>(g_h)[i] = z;
}
__global__ void k_pool_zero() {
    int i = blockIdx.x * blockDim.x + threadIdx.x;      // 65*256 = 16640
    if (i < NGR * NF) g_pool[i] = 0.0f;
    else if (i < NGR * NF + NGR) g_cnt[i - NGR * NF] = 0.0f;
}

// --------------- node GEMM: h_src / h_dst = x @ W + b ---------------------
// tile: 32 nodes x 128 cols, 256 threads, 4x4 register blocking
__global__ __launch_bounds__(256) void k_node_gemm(
    const float* __restrict__ Wsrc, const float* __restrict__ bsrc,
    const float* __restrict__ Wdst, const float* __restrict__ bdst, int l) {
    const float* W = (blockIdx.y == 0 ? Wsrc : Wdst) + l * NF * NF2;
    const float* b = (blockIdx.y == 0 ? bsrc : bdst) + l * NF2;
    float*       H = (blockIdx.y == 0 ? g_hs : g_hd);

    __shared__ float Ws[NF * NF2];       // 32 KB
    __shared__ float xT[NF][36];         // transposed x tile (stride 36: 16B-aligned rows)

    const int tid = threadIdx.x;
    for (int i = tid; i < NF * NF2 / 4; i += 256)
        reinterpret_cast<float4*>(Ws)[i] = reinterpret_cast<const float4*>(W)[i];

    const int nb = blockIdx.x * 32;
    for (int q = tid; q < 32 * 16; q += 256) {          // 512 float4
        int n = q >> 4, kk = q & 15;
        float4 v = reinterpret_cast<const float4*>(g_x + (nb + n) * NF)[kk];
        xT[kk * 4 + 0][n] = v.x; xT[kk * 4 + 1][n] = v.y;
        xT[kk * 4 + 2][n] = v.z; xT[kk * 4 + 3][n] = v.w;
    }
    __syncthreads();

    const int cc = tid & 31;             // col group (4 cols)
    const int ng = tid >> 5;             // node group (4 nodes)
    float4 acc0 = make_float4(0, 0, 0, 0), acc1 = acc0, acc2 = acc0, acc3 = acc0;

#pragma unroll 8
    for (int k = 0; k < NF; ++k) {
        float4 xv = *reinterpret_cast<float4*>(&xT[k][ng * 4]);
        float4 wv = reinterpret_cast<float4*>(&Ws[k * NF2])[cc];
        acc0.x += xv.x * wv.x; acc0.y += xv.x * wv.y; acc0.z += xv.x * wv.z; acc0.w += xv.x * wv.w;
        acc1.x += xv.y * wv.x; acc1.y += xv.y * wv.y; acc1.z += xv.y * wv.z; acc1.w += xv.y * wv.w;
        acc2.x += xv.z * wv.x; acc2.y += xv.z * wv.y; acc2.z += xv.z * wv.z; acc2.w += xv.z * wv.w;
        acc3.x += xv.w * wv.x; acc3.y += xv.w * wv.y; acc3.z += xv.w * wv.z; acc3.w += xv.w * wv.w;
    }
    float4 bv = reinterpret_cast<const float4*>(b)[cc];
    float4 accs[4] = {acc0, acc1, acc2, acc3};
#pragma unroll
    for (int i = 0; i < 4; ++i) {
        float4 o = make_float4(accs[i].x + bv.x, accs[i].y + bv.y,
                               accs[i].z + bv.z, accs[i].w + bv.w);
        reinterpret_cast<float4*>(H + (nb + ng * 4 + i) * NF2)[cc] = o;
    }
}

// --------------- per-edge message recompute -------------------------------
__device__ __forceinline__ float4 edge_m(int e, int lane,
                                         const int* __restrict__ src,
                                         const int* __restrict__ dst,
                                         const float* __restrict__ dist,
                                         int* outd) {
    int s = __ldg(&src[e]);
    int d = __ldg(&dst[e]);
    float t = __ldg(&dist[e]) * (TAB / 8.0f);
    int i0 = min((int)t, TAB - 1);
    float f = t - (float)i0;
    float4 hs = *reinterpret_cast<const float4*>(g_hs + s * NF2 + lane * 4);
    float4 hd = *reinterpret_cast<const float4*>(g_hd + d * NF2 + lane * 4);
    float4 t0 = *reinterpret_cast<const float4*>(g_tab + i0 * NF2 + lane * 4);
    float4 t1 = *reinterpret_cast<const float4*>(g_tab + (i0 + 1) * NF2 + lane * 4);
    float4 m;
    m.x = hs.x + hd.x + t0.x + f * (t1.x - t0.x);
    m.y = hs.y + hd.y + t0.y + f * (t1.y - t0.y);
    m.z = hs.z + hd.z + t0.z + f * (t1.z - t0.z);
    m.w = hs.w + hd.w + t0.w + f * (t1.w - t0.w);
    *outd = d;
    return m;
}

// --------------- pass A: per-channel sum/sumsq of m over edges ------------
__global__ __launch_bounds__(256) void k_edge_stats(const int* __restrict__ src,
                                                    const int* __restrict__ dst,
                                                    const float* __restrict__ dist) {
    const int lane = threadIdx.x & 31;
    const int wid  = (blockIdx.x * blockDim.x + threadIdx.x) >> 5;
    const int nw   = (gridDim.x * blockDim.x) >> 5;
    float4 s4 = make_float4(0, 0, 0, 0), q4 = s4;
    for (int e = wid; e < NE; e += nw) {
        int dd;
        float4 m = edge_m(e, lane, src, dst, dist, &dd);
        s4.x += m.x; s4.y += m.y; s4.z += m.z; s4.w += m.w;
        q4.x += m.x * m.x; q4.y += m.y * m.y; q4.z += m.z * m.z; q4.w += m.w * m.w;
    }
    __shared__ float ss[NF2], sq[NF2];
    if (threadIdx.x < NF2) { ss[threadIdx.x] = 0.0f; sq[threadIdx.x] = 0.0f; }
    __syncthreads();
    atomicAdd(&ss[lane * 4 + 0], s4.x); atomicAdd(&ss[lane * 4 + 1], s4.y);
    atomicAdd(&ss[lane * 4 + 2], s4.z); atomicAdd(&ss[lane * 4 + 3], s4.w);
    atomicAdd(&sq[lane * 4 + 0], q4.x); atomicAdd(&sq[lane * 4 + 1], q4.y);
    atomicAdd(&sq[lane * 4 + 2], q4.z); atomicAdd(&sq[lane * 4 + 3], q4.w);
    __syncthreads();
    if (threadIdx.x < NF2) {
        atomicAdd(&g_esum[threadIdx.x], ss[threadIdx.x]);
        atomicAdd(&g_esq [threadIdx.x], sq[threadIdx.x]);
    }
}

// --------------- fold BN into y = A*m + B ---------------------------------
__global__ void k_finalize(const float* __restrict__ gm, const float* __restrict__ bm, int l) {
    int c = threadIdx.x;                                // 128
    float mean = g_esum[c] * (1.0f / NE);
    float var  = fmaxf(g_esq[c] * (1.0f / NE) - mean * mean, 0.0f);
    float A = gm[l * NF2 + c] * rsqrtf(var + BN_EPS);
    g_AB[c]       = A;
    g_AB[NF2 + c] = bm[l * NF2 + c] - mean * A;
}

// --------------- pass B: normalize, gate, scatter to dst ------------------
__global__ __launch_bounds__(256) void k_edge_apply(const int* __restrict__ src,
                                                    const int* __restrict__ dst,
                                                    const float* __restrict__ dist) {
    const int lane = threadIdx.x & 31;
    const int wid  = (blockIdx.x * blockDim.x + threadIdx.x) >> 5;
    const int nw   = (gridDim.x * blockDim.x) >> 5;
    const float4 A = reinterpret_cast<const float4*>(g_AB)[lane];
    const float4 B = reinterpret_cast<const float4*>(g_AB + NF2)[lane];
    for (int e = wid; e < NE; e += nw) {
        int dd;
        float4 m = edge_m(e, lane, src, dst, dist, &dd);
        float4 y;
        y.x = A.x * m.x + B.x; y.y = A.y * m.y + B.y;
        y.z = A.z * m.z + B.z; y.w = A.w * m.w + B.w;
        // lanes 0..15 own gate channels 4L..4L+3; partner channels live on lane L+16
        float px = __shfl_down_sync(0xffffffffu, y.x, 16);
        float py = __shfl_down_sync(0xffffffffu, y.y, 16);
        float pz = __shfl_down_sync(0xffffffffu, y.z, 16);
        float pw = __shfl_down_sync(0xffffffffu, y.w, 16);
        if (lane < 16) {
            float4 o;
            o.x = sig_f(y.x) * sp_f(px);
            o.y = sig_f(y.y) * sp_f(py);
            o.z = sig_f(y.z) * sp_f(pz);
            o.w = sig_f(y.w) * sp_f(pw);
            atomicAdd(reinterpret_cast<float4*>(g_h + dd * NF + lane * 4), o);
        }
    }
}

// --------------- node BN stats --------------------------------------------
__global__ __launch_bounds__(256) void k_node_stats() {
    const int c = threadIdx.x & 63;
    int n = (blockIdx.x * blockDim.x + threadIdx.x) >> 6;
    const int stride = (gridDim.x * blockDim.x) >> 6;
    float s = 0.0f, q = 0.0f;
    for (; n < NN; n += stride) {
        float v = g_h[n * NF + c];
        s += v; q += v * v;
    }
    __shared__ float ss[NF], sq[NF];
    if (threadIdx.x < NF) { ss[threadIdx.x] = 0.0f; sq[threadIdx.x] = 0.0f; }
    __syncthreads();
    atomicAdd(&ss[c], s);
    atomicAdd(&sq[c], q);
    __syncthreads();
    if (threadIdx.x < NF) {
        atomicAdd(&g_nsum[threadIdx.x], ss[threadIdx.x]);
        atomicAdd(&g_nsq [threadIdx.x], sq[threadIdx.x]);
    }
}

// --------------- x = softplus(x + BN(h)) ----------------------------------
__global__ __launch_bounds__(256) void k_node_update(const float* __restrict__ gb,
                                                     const float* __restrict__ bb, int l) {
    int i = blockIdx.x * blockDim.x + threadIdx.x;
    const int total = NN * NF;
    for (; i < total; i += gridDim.x * blockDim.x) {
        int c = i & 63;
        float mean = g_nsum[c] * (1.0f / NN);
        float var  = fmaxf(g_nsq[c] * (1.0f / NN) - mean * mean, 0.0f);
        float A = gb[l * NF + c] * rsqrtf(var + BN_EPS);
        float B = bb[l * NF + c] - mean * A;
        float v = g_x[i] + A * g_h[i] + B;
        g_x[i] = sp_f(v);
    }
}

// --------------- readout --------------------------------------------------
__global__ __launch_bounds__(256) void k_pool(const int* __restrict__ gid) {
    const int lane = threadIdx.x & 31;
    int w = (blockIdx.x * blockDim.x + threadIdx.x) >> 5;
    const int nw = (gridDim.x * blockDim.x) >> 5;
    for (int n = w; n < NN; n += nw) {
        int g = __ldg(&gid[n]);
        if (lane < 16) {
            float4 v = reinterpret_cast<const float4*>(g_x + n * NF)[lane];
            atomicAdd(reinterpret_cast<float4*>(g_pool + g * NF + lane * 4), v);
        } else if (lane == 16) {
            atomicAdd(&g_cnt[g], 1.0f);
        }
    }
}
__global__ void k_div(float* __restrict__ out) {
    int i = blockIdx.x * blockDim.x + threadIdx.x;      // 64*256 = 16384
    if (i < NGR * NF)
        out[i] = g_pool[i] / fmaxf(g_cnt[i >> 6], 1.0f);
}

// ---------------- launcher ------------------------------------------------
extern "C" void kernel_launch(void* const* d_in, const int* in_sizes, int n_in,
                              void* d_out, int out_size) {
    const int*   atom_types = (const int*)  d_in[0];
    const float* distances  = (const float*)d_in[1];
    const int*   src        = (const int*)  d_in[2];
    const int*   dst        = (const int*)  d_in[3];
    const int*   gid        = (const int*)  d_in[4];
    // n_graphs may or may not be materialized as an input at slot 5
    const int base = (in_sizes[5] == 1) ? 6 : 5;
    const float* atom_table = (const float*)d_in[base + 0];
    const float* W_embed    = (const float*)d_in[base + 1];
    const float* b_embed    = (const float*)d_in[base + 2];
    const float* W_src      = (const float*)d_in[base + 3];
    const float* b_src      = (const float*)d_in[base + 4];
    const float* W_dst      = (const float*)d_in[base + 5];
    const float* b_dst      = (const float*)d_in[base + 6];
    const float* W_edge     = (const float*)d_in[base + 7];
    const float* b_edge     = (const float*)d_in[base + 8];
    const float* g_msg      = (const float*)d_in[base + 9];
    const float* beta_msg   = (const float*)d_in[base + 10];
    const float* g_bn       = (const float*)d_in[base + 11];
    const float* beta_bn    = (const float*)d_in[base + 12];
    float* out = (float*)d_out;

    k_emb<<<NAT, NF>>>(atom_table, W_embed, b_embed);
    k_gather_x<<<1024, 256>>>(atom_types);

    for (int l = 0; l < NL; ++l) {
        k_tab<<<TAB + 1, NF2>>>(W_edge, b_edge, l);
        k_zero_small<<<1, 384>>>();
        k_zero_h<<<1024, 256>>>();
        k_node_gemm<<<dim3(NN / 32, 2), 256>>>(W_src, b_src, W_dst, b_dst, l);
        k_edge_stats<<<2048, 256>>>(src, dst, distances);
        k_finalize<<<1, NF2>>>(g_msg, beta_msg, l);
        k_edge_apply<<<2048, 256>>>(src, dst, distances);
        k_node_stats<<<512, 256>>>();
        k_node_update<<<1024, 256>>>(g_bn, beta_bn, l);
    }

    k_pool_zero<<<65, 256>>>();
    k_pool<<<512, 256>>>(gid);
    k_div<<<64, 256>>>(out);
}

// round 4
// speedup vs baseline: 1.2598x; 1.2598x over previous
#include <cuda_runtime.h>
#include <cuda_fp16.h>

// ---------------- problem constants (fixed by the dataset) ----------------
#define NN   100000     // nodes
#define NE   1600000    // edges
#define NGR  256        // graphs
#define NF   64         // node feat
#define NF2  128        // 2*NF
#define EFB  40         // rbf bins
#define NL   3          // layers
#define NAT  95         // atom types
#define NAF  200        // atom feat
#define TAB  2048       // e_lin interpolation intervals over [0,8]
#define BN_EPS 1e-5f

// ---------------- persistent device scratch (no runtime allocation) -------
__device__ float  g_x   [NN * NF];          // node features (fp32)
__device__ __half g_hs  [NN * NF2];         // x @ W_src + b   (fp16)
__device__ __half g_hd  [NN * NF2];         // x @ W_dst + b   (fp16)
__device__ float  g_h   [NN * NF];          // scattered messages (fp32 accum)
__device__ __half g_tab [(TAB + 1) * NF2];  // e_lin(d) lerp table (fp16)
__device__ float  g_emb [NAT * NF];         // atom_table @ W_embed + b
__device__ float  g_esum[NF2];
__device__ float  g_esq [NF2];
__device__ float  g_AB  [2 * NF2];          // folded BN: A*m+B
__device__ float  g_nsum[NF];
__device__ float  g_nsq [NF];
__device__ float  g_pool[NGR * NF];
__device__ float  g_cnt [NGR];

// ---------------- helpers -------------------------------------------------
__device__ __forceinline__ float sp_f(float x) {   // softplus
    return fmaxf(x, 0.0f) + __logf(1.0f + __expf(-fabsf(x)));
}
__device__ __forceinline__ float sig_f(float x) {
    return __fdividef(1.0f, 1.0f + __expf(-x));
}

// --------------- 0a: fold atom featurizer + embedding into [95,64] --------
__global__ void k_emb(const float* __restrict__ at, const float* __restrict__ W,
                      const float* __restrict__ b) {
    int a = blockIdx.x, c = threadIdx.x;               // 95 blocks x 64 threads
    float acc = b[c];
    for (int k = 0; k < NAF; ++k)
        acc += at[a * NAF + k] * W[k * NF + c];
    g_emb[a * NF + c] = acc;
}

// --------------- 0b: x[n] = emb[type[n]] ----------------------------------
__global__ void k_gather_x(const int* __restrict__ types) {
    int i = blockIdx.x * blockDim.x + threadIdx.x;
    const int total = NN * (NF / 4);
    for (; i < total; i += gridDim.x * blockDim.x) {
        int n = i >> 4, j = i & 15;
        int t = __ldg(&types[n]);
        reinterpret_cast<float4*>(g_x)[i] =
            reinterpret_cast<const float4*>(g_emb)[t * (NF / 4) + j];
    }
}

// --------------- per-layer: build e_lin(d) lerp table (fp16) --------------
__global__ void k_tab(const float* __restrict__ We, const float* __restrict__ be, int l) {
    __shared__ float phi[EFB];
    const float d = blockIdx.x * (8.0f / TAB);
    const int c = threadIdx.x;                          // 128 threads
    if (c < EFB) {
        float ctr = c * (8.0f / 39.0f);                 // linspace(0,8,40)
        float x = d - ctr;
        phi[c] = expf(-4.875f * x * x);                 // gamma = 39/8
    }
    __syncthreads();
    const float* W = We + l * EFB * NF2;
    float acc = be[l * NF2 + c];
#pragma unroll
    for (int k = 0; k < EFB; ++k)
        acc += phi[k] * W[k * NF2 + c];
    g_tab[blockIdx.x * NF2 + c] = __float2half_rn(acc);
}

// --------------- small zeroing kernels ------------------------------------
__global__ void k_zero_small() {
    int t = threadIdx.x;                                // 384 threads
    if (t < NF2) { g_esum[t] = 0.0f; g_esq[t] = 0.0f; }
    else if (t < NF2 + NF)       g_nsum[t - NF2] = 0.0f;
    else if (t < NF2 + 2 * NF)   g_nsq [t - NF2 - NF] = 0.0f;
}
__global__ void k_zero_h() {
    int i = blockIdx.x * blockDim.x + threadIdx.x;
    const int total = NN * (NF / 4);
    float4 z = make_float4(0.f, 0.f, 0.f, 0.f);
    for (; i < total; i += gridDim.x * blockDim.x)
        reinterpret_cast<float4*>(g_h)[i] = z;
}
__global__ void k_pool_zero() {
    int i = blockIdx.x * blockDim.x + threadIdx.x;      // 65*256 = 16640
    if (i < NGR * NF) g_pool[i] = 0.0f;
    else if (i < NGR * NF + NGR) g_cnt[i - NGR * NF] = 0.0f;
}

// --------------- node GEMM: h_src / h_dst = x @ W + b  (fp16 output) ------
// tile: 32 nodes x 128 cols, 256 threads, 4x4 register blocking
__global__ __launch_bounds__(256) void k_node_gemm(
    const float* __restrict__ Wsrc, const float* __restrict__ bsrc,
    const float* __restrict__ Wdst, const float* __restrict__ bdst, int l) {
    const float* W = (blockIdx.y == 0 ? Wsrc : Wdst) + l * NF * NF2;
    const float* b = (blockIdx.y == 0 ? bsrc : bdst) + l * NF2;
    __half*      H = (blockIdx.y == 0 ? g_hs : g_hd);

    __shared__ float Ws[NF * NF2];       // 32 KB
    __shared__ float xT[NF][36];         // transposed x tile

    const int tid = threadIdx.x;
    for (int i = tid; i < NF * NF2 / 4; i += 256)
        reinterpret_cast<float4*>(Ws)[i] = reinterpret_cast<const float4*>(W)[i];

    const int nb = blockIdx.x * 32;
    for (int q = tid; q < 32 * 16; q += 256) {          // 512 float4
        int n = q >> 4, kk = q & 15;
        float4 v = reinterpret_cast<const float4*>(g_x + (nb + n) * NF)[kk];
        xT[kk * 4 + 0][n] = v.x; xT[kk * 4 + 1][n] = v.y;
        xT[kk * 4 + 2][n] = v.z; xT[kk * 4 + 3][n] = v.w;
    }
    __syncthreads();

    const int cc = tid & 31;             // col group (4 cols)
    const int ng = tid >> 5;             // node group (4 nodes)
    float4 acc0 = make_float4(0, 0, 0, 0), acc1 = acc0, acc2 = acc0, acc3 = acc0;

#pragma unroll 8
    for (int k = 0; k < NF; ++k) {
        float4 xv = *reinterpret_cast<float4*>(&xT[k][ng * 4]);
        float4 wv = reinterpret_cast<float4*>(&Ws[k * NF2])[cc];
        acc0.x += xv.x * wv.x; acc0.y += xv.x * wv.y; acc0.z += xv.x * wv.z; acc0.w += xv.x * wv.w;
        acc1.x += xv.y * wv.x; acc1.y += xv.y * wv.y; acc1.z += xv.y * wv.z; acc1.w += xv.y * wv.w;
        acc2.x += xv.z * wv.x; acc2.y += xv.z * wv.y; acc2.z += xv.z * wv.z; acc2.w += xv.z * wv.w;
        acc3.x += xv.w * wv.x; acc3.y += xv.w * wv.y; acc3.z += xv.w * wv.z; acc3.w += xv.w * wv.w;
    }
    float4 bv = reinterpret_cast<const float4*>(b)[cc];
    float4 accs[4] = {acc0, acc1, acc2, acc3};
#pragma unroll
    for (int i = 0; i < 4; ++i) {
        __half2 lo = __floats2half2_rn(accs[i].x + bv.x, accs[i].y + bv.y);
        __half2 hi = __floats2half2_rn(accs[i].z + bv.z, accs[i].w + bv.w);
        uint2 pk;
        pk.x = *reinterpret_cast<unsigned*>(&lo);
        pk.y = *reinterpret_cast<unsigned*>(&hi);
        *reinterpret_cast<uint2*>(H + (nb + ng * 4 + i) * NF2 + cc * 4) = pk;
    }
}

// --------------- per-edge message recompute (8 channels / lane) -----------
// Lanes 0..15 process edge e (half 0), lanes 16..31 edge e+1 (half 1).
// Sub-lane t in [0,16) owns channels 8t..8t+7 via one LDG.128 per operand.
struct M8 { float2 v[4]; };

__device__ __forceinline__ M8 edge_m8(int e, int t,
                                      const int* __restrict__ src,
                                      const int* __restrict__ dst,
                                      const float* __restrict__ dist,
                                      int* outd) {
    int s = __ldg(&src[e]);
    int d = __ldg(&dst[e]);
    float ft = __ldg(&dist[e]) * (TAB / 8.0f);
    int i0 = min((int)ft, TAB - 1);
    float f = ft - (float)i0;
    uint4 ua = reinterpret_cast<const uint4*>(g_hs)[s * 16 + t];
    uint4 ub = reinterpret_cast<const uint4*>(g_hd)[d * 16 + t];
    uint4 u0 = reinterpret_cast<const uint4*>(g_tab)[i0 * 16 + t];
    uint4 u1 = reinterpret_cast<const uint4*>(g_tab)[(i0 + 1) * 16 + t];
    const __half2* ha = reinterpret_cast<const __half2*>(&ua);
    const __half2* hb = reinterpret_cast<const __half2*>(&ub);
    const __half2* h0 = reinterpret_cast<const __half2*>(&u0);
    const __half2* h1 = reinterpret_cast<const __half2*>(&u1);
    M8 m;
#pragma unroll
    for (int j = 0; j < 4; ++j) {
        float2 va = __half22float2(ha[j]);
        float2 vb = __half22float2(hb[j]);
        float2 v0 = __half22float2(h0[j]);
        float2 v1 = __half22float2(h1[j]);
        m.v[j].x = va.x + vb.x + v0.x + f * (v1.x - v0.x);
        m.v[j].y = va.y + vb.y + v0.y + f * (v1.y - v0.y);
    }
    *outd = d;
    return m;
}

// --------------- pass A: per-channel sum/sumsq of m over edges ------------
__global__ __launch_bounds__(256) void k_edge_stats(const int* __restrict__ src,
                                                    const int* __restrict__ dst,
                                                    const float* __restrict__ dist) {
    const int lane = threadIdx.x & 31;
    const int half = lane >> 4;
    const int t    = lane & 15;
    const int wid  = (blockIdx.x * blockDim.x + threadIdx.x) >> 5;
    const int nw   = (gridDim.x * blockDim.x) >> 5;
    float2 s2[4], q2[4];
#pragma unroll
    for (int j = 0; j < 4; ++j) { s2[j] = make_float2(0, 0); q2[j] = make_float2(0, 0); }

    for (int e0 = wid * 2; e0 < NE; e0 += nw * 2) {
        int dd;
        M8 m = edge_m8(e0 + half, t, src, dst, dist, &dd);
#pragma unroll
        for (int j = 0; j < 4; ++j) {
            s2[j].x += m.v[j].x;           s2[j].y += m.v[j].y;
            q2[j].x += m.v[j].x * m.v[j].x; q2[j].y += m.v[j].y * m.v[j].y;
        }
    }
    __shared__ float ss[NF2], sq[NF2];
    if (threadIdx.x < NF2) { ss[threadIdx.x] = 0.0f; sq[threadIdx.x] = 0.0f; }
    __syncthreads();
#pragma unroll
    for (int j = 0; j < 4; ++j) {
        atomicAdd(&ss[t * 8 + 2 * j],     s2[j].x);
        atomicAdd(&ss[t * 8 + 2 * j + 1], s2[j].y);
        atomicAdd(&sq[t * 8 + 2 * j],     q2[j].x);
        atomicAdd(&sq[t * 8 + 2 * j + 1], q2[j].y);
    }
    __syncthreads();
    if (threadIdx.x < NF2) {
        atomicAdd(&g_esum[threadIdx.x], ss[threadIdx.x]);
        atomicAdd(&g_esq [threadIdx.x], sq[threadIdx.x]);
    }
}

// --------------- fold BN into y = A*m + B ---------------------------------
__global__ void k_finalize(const float* __restrict__ gm, const float* __restrict__ bm, int l) {
    int c = threadIdx.x;                                // 128
    float mean = g_esum[c] * (1.0f / NE);
    float var  = fmaxf(g_esq[c] * (1.0f / NE) - mean * mean, 0.0f);
    float A = gm[l * NF2 + c] * rsqrtf(var + BN_EPS);
    g_AB[c]       = A;
    g_AB[NF2 + c] = bm[l * NF2 + c] - mean * A;
}

// --------------- pass B: normalize, gate, scatter to dst ------------------
__global__ __launch_bounds__(256) void k_edge_apply(const int* __restrict__ src,
                                                    const int* __restrict__ dst,
                                                    const float* __restrict__ dist) {
    const int lane = threadIdx.x & 31;
    const int half = lane >> 4;
    const int t    = lane & 15;
    const int wid  = (blockIdx.x * blockDim.x + threadIdx.x) >> 5;
    const int nw   = (gridDim.x * blockDim.x) >> 5;

    const float4 A0 = reinterpret_cast<const float4*>(g_AB)[t * 2];
    const float4 A1 = reinterpret_cast<const float4*>(g_AB)[t * 2 + 1];
    const float4 B0 = reinterpret_cast<const float4*>(g_AB + NF2)[t * 2];
    const float4 B1 = reinterpret_cast<const float4*>(g_AB + NF2)[t * 2 + 1];

    for (int e0 = wid * 2; e0 < NE; e0 += nw * 2) {
        int dd;
        M8 m = edge_m8(e0 + half, t, src, dst, dist, &dd);
        float y[8];
        y[0] = A0.x * m.v[0].x + B0.x;  y[1] = A0.y * m.v[0].y + B0.y;
        y[2] = A0.z * m.v[1].x + B0.z;  y[3] = A0.w * m.v[1].y + B0.w;
        y[4] = A1.x * m.v[2].x + B1.x;  y[5] = A1.y * m.v[2].y + B1.y;
        y[6] = A1.z * m.v[3].x + B1.z;  y[7] = A1.w * m.v[3].y + B1.w;
        // partner channels (c+64) live on sub-lane t+8 of the same half-warp
        float p[8];
#pragma unroll
        for (int j = 0; j < 8; ++j)
            p[j] = __shfl_down_sync(0xffffffffu, y[j], 8);
        if (t < 8) {
            float4 o0, o1;
            o0.x = sig_f(y[0]) * sp_f(p[0]); o0.y = sig_f(y[1]) * sp_f(p[1]);
            o0.z = sig_f(y[2]) * sp_f(p[2]); o0.w = sig_f(y[3]) * sp_f(p[3]);
            o1.x = sig_f(y[4]) * sp_f(p[4]); o1.y = sig_f(y[5]) * sp_f(p[5]);
            o1.z = sig_f(y[6]) * sp_f(p[6]); o1.w = sig_f(y[7]) * sp_f(p[7]);
            float* base = g_h + dd * NF + t * 8;
            atomicAdd(reinterpret_cast<float4*>(base),     o0);
            atomicAdd(reinterpret_cast<float4*>(base + 4), o1);
        }
    }
}

// --------------- node BN stats --------------------------------------------
__global__ __launch_bounds__(256) void k_node_stats() {
    const int c = threadIdx.x & 63;
    int n = (blockIdx.x * blockDim.x + threadIdx.x) >> 6;
    const int stride = (gridDim.x * blockDim.x) >> 6;
    float s = 0.0f, q = 0.0f;
    for (; n < NN; n += stride) {
        float v = g_h[n * NF + c];
        s += v; q += v * v;
    }
    __shared__ float ss[NF], sq[NF];
    if (threadIdx.x < NF) { ss[threadIdx.x] = 0.0f; sq[threadIdx.x] = 0.0f; }
    __syncthreads();
    atomicAdd(&ss[c], s);
    atomicAdd(&sq[c], q);
    __syncthreads();
    if (threadIdx.x < NF) {
        atomicAdd(&g_nsum[threadIdx.x], ss[threadIdx.x]);
        atomicAdd(&g_nsq [threadIdx.x], sq[threadIdx.x]);
    }
}

// --------------- x = softplus(x + BN(h)) ----------------------------------
__global__ __launch_bounds__(256) void k_node_update(const float* __restrict__ gb,
                                                     const float* __restrict__ bb, int l) {
    int i = blockIdx.x * blockDim.x + threadIdx.x;
    const int total = NN * NF;
    for (; i < total; i += gridDim.x * blockDim.x) {
        int c = i & 63;
        float mean = g_nsum[c] * (1.0f / NN);
        float var  = fmaxf(g_nsq[c] * (1.0f / NN) - mean * mean, 0.0f);
        float A = gb[l * NF + c] * rsqrtf(var + BN_EPS);
        float B = bb[l * NF + c] - mean * A;
        float v = g_x[i] + A * g_h[i] + B;
        g_x[i] = sp_f(v);
    }
}

// --------------- readout --------------------------------------------------
__global__ __launch_bounds__(256) void k_pool(const int* __restrict__ gid) {
    const int lane = threadIdx.x & 31;
    int w = (blockIdx.x * blockDim.x + threadIdx.x) >> 5;
    const int nw = (gridDim.x * blockDim.x) >> 5;
    for (int n = w; n < NN; n += nw) {
        int g = __ldg(&gid[n]);
        if (lane < 16) {
            float4 v = reinterpret_cast<const float4*>(g_x + n * NF)[lane];
            atomicAdd(reinterpret_cast<float4*>(g_pool + g * NF + lane * 4), v);
        } else if (lane == 16) {
            atomicAdd(&g_cnt[g], 1.0f);
        }
    }
}
__global__ void k_div(float* __restrict__ out) {
    int i = blockIdx.x * blockDim.x + threadIdx.x;      // 64*256 = 16384
    if (i < NGR * NF)
        out[i] = g_pool[i] / fmaxf(g_cnt[i >> 6], 1.0f);
}

// ---------------- launcher ------------------------------------------------
extern "C" void kernel_launch(void* const* d_in, const int* in_sizes, int n_in,
                              void* d_out, int out_size) {
    const int*   atom_types = (const int*)  d_in[0];
    const float* distances  = (const float*)d_in[1];
    const int*   src        = (const int*)  d_in[2];
    const int*   dst        = (const int*)  d_in[3];
    const int*   gid        = (const int*)  d_in[4];
    const int base = (in_sizes[5] == 1) ? 6 : 5;   // n_graphs may be materialized
    const float* atom_table = (const float*)d_in[base + 0];
    const float* W_embed    = (const float*)d_in[base + 1];
    const float* b_embed    = (const float*)d_in[base + 2];
    const float* W_src      = (const float*)d_in[base + 3];
    const float* b_src      = (const float*)d_in[base + 4];
    const float* W_dst      = (const float*)d_in[base + 5];
    const float* b_dst      = (const float*)d_in[base + 6];
    const float* W_edge     = (const float*)d_in[base + 7];
    const float* b_edge     = (const float*)d_in[base + 8];
    const float* g_msg      = (const float*)d_in[base + 9];
    const float* beta_msg   = (const float*)d_in[base + 10];
    const float* g_bn       = (const float*)d_in[base + 11];
    const float* beta_bn    = (const float*)d_in[base + 12];
    float* out = (float*)d_out;

    k_emb<<<NAT, NF>>>(atom_table, W_embed, b_embed);
    k_gather_x<<<1024, 256>>>(atom_types);

    for (int l = 0; l < NL; ++l) {
        k_tab<<<TAB + 1, NF2>>>(W_edge, b_edge, l);
        k_zero_small<<<1, 384>>>();
        k_zero_h<<<1024, 256>>>();
        k_node_gemm<<<dim3(NN / 32, 2), 256>>>(W_src, b_src, W_dst, b_dst, l);
        k_edge_stats<<<2048, 256>>>(src, dst, distances);
        k_finalize<<<1, NF2>>>(g_msg, beta_msg, l);
        k_edge_apply<<<2048, 256>>>(src, dst, distances);
        k_node_stats<<<512, 256>>>();
        k_node_update<<<1024, 256>>>(g_bn, beta_bn, l);
    }

    k_pool_zero<<<65, 256>>>();
    k_pool<<<512, 256>>>(gid);
    k_div<<<64, 256>>>(out);
}